// round 7
// baseline (speedup 1.0000x reference)
#include <cuda_runtime.h>
#include <math.h>
#include <stdint.h>

#define SLOPE 0.01f
constexpr float RCOEF = 1.0f - SLOPE;

// -------- problem constants --------
constexpr int Dd    = 32;
constexpr int Hh    = 128;
constexpr int Bb    = 64;
constexpr int Tt    = 514;
constexpr int TTt   = 512;
constexpr int NTOT  = Bb * TTt;          // 32768
constexpr int NTILE = 128;
constexpr int NTILES = NTOT / NTILE;     // 256

// output layout (reference return order, concatenated)
constexpr size_t RES_OFF  = 0;                        // (64,512,32)
constexpr size_t SUM_OFF  = (size_t)Bb * TTt * Dd;    // (64,)
constexpr size_t HIST_OFF = SUM_OFF + Bb;             // (32,32768,1,64)

// -------- shared offsets (u32 units) --------
// x packed: 129 rows x 64 words (16 16B-units: [hi(c),lo(c),hi(c+4),lo(c+4)], XOR-swizzled)
// W1 packed: 128 rows x 128 words (32 units, same scheme over k=0..63)
constexpr int O_XP    = 0;                    // 129*64 = 8256
constexpr int O_WP    = 8256;                 // 128*128 = 16384
constexpr int O_MASK  = 24640;                // 128 rows x 4 words
constexpr int O_S     = 25152;                // 64
constexpr int O_WLAST = 25216;                // 128
constexpr int O_B1    = 25344;                // 128
constexpr int O_W2    = 25472;                // 128
constexpr int O_YY    = 25600;                // 132
constexpr int O_RS    = 25732;                // 128
constexpr int O_JS    = 25860;                // 128
constexpr int O_RED   = 25988;                // 4
constexpr int SMEM_U32 = 25992;
constexpr int SMEM_BYTES = SMEM_U32 * 4;      // 103968

__device__ __forceinline__ uint32_t f2tf32(float f) {
    uint32_t u;
    asm("cvt.rna.tf32.f32 %0, %1;" : "=r"(u) : "f"(f));
    return u;
}
__device__ __forceinline__ void split_tf32(float v, uint32_t& hi, uint32_t& lo) {
    hi = f2tf32(v);
    lo = f2tf32(v - __uint_as_float(hi));
}

__device__ __forceinline__ void mma8(float* d, const uint32_t* a, uint32_t b0, uint32_t b1) {
    asm volatile(
        "mma.sync.aligned.m16n8k8.row.col.f32.tf32.tf32.f32 "
        "{%0,%1,%2,%3}, {%4,%5,%6,%7}, {%8,%9}, {%0,%1,%2,%3};"
        : "+f"(d[0]), "+f"(d[1]), "+f"(d[2]), "+f"(d[3])
        : "r"(a[0]), "r"(a[1]), "r"(a[2]), "r"(a[3]), "r"(b0), "r"(b1));
}

// packed word offset for element (row, col) within a 2-lag-k tile; colsPerRowU = units per row
// unit = (4*(c>>3) + (c&3)) ^ ((r&1)<<2); word-in-unit = (c&4)?2:0  (+0=hi, +1=lo)
__device__ __forceinline__ int pk_off(int r, int c, int rowWords) {
    int u = ((4 * (c >> 3) + (c & 3)) ^ ((r & 1) << 2));
    return r * rowWords + u * 4 + ((c & 4) ? 2 : 0);
}

__global__ void zero_sum_kernel(float* out) { out[SUM_OFF + threadIdx.x] = 0.0f; }

extern __shared__ uint32_t smemu[];

__global__ __launch_bounds__(256, 2)
void fused_mma(const float* __restrict__ x,  const float* __restrict__ W1,
               const float* __restrict__ b1, const float* __restrict__ W2,
               const float* __restrict__ b2, float* __restrict__ out)
{
    float* sf = (float*)smemu;
    const int tid  = threadIdx.x;
    const int lane = tid & 31;
    const int w    = tid >> 5;
    const int lr   = lane >> 2;   // 0..7
    const int lc   = lane & 3;    // 0..3

    const int d  = blockIdx.x;
    const int n0 = blockIdx.y * NTILE;
    const int bb = n0 / TTt;
    const int t0 = n0 % TTt;

    // ---------------- preamble: pack hi/lo tiles ----------------
    {
        const float* W1g = W1 + (size_t)d * Hh * 65;
        for (int idx = tid; idx < Hh * 65; idx += 256) {
            int h = idx / 65;
            int k = idx - h * 65;
            float v = W1g[idx];
            if (k == 64) sf[O_WLAST + h] = v;
            else {
                uint32_t hi, lo;
                split_tf32(v, hi, lo);
                int o = O_WP + pk_off(h, k, 128);
                smemu[o]     = hi;
                smemu[o + 1] = lo;
            }
        }
        const float* xg = x + ((size_t)bb * Tt + t0) * Dd;
        for (int idx = tid; idx < 130 * 32; idx += 256) {
            int r = idx >> 5, c = idx & 31;
            float v = xg[idx];
            if (c == d) sf[O_YY + r] = v;
            if (r < 129) {
                uint32_t hi, lo;
                split_tf32(v, hi, lo);
                int o = O_XP + pk_off(r, c, 64);
                smemu[o]     = hi;
                smemu[o + 1] = lo;
            }
        }
        if (tid < 128) {
            sf[O_B1 + tid] = b1[(size_t)d * Hh + tid];
            sf[O_W2 + tid] = W2[(size_t)d * Hh + tid];
            sf[O_RS + tid] = 0.0f;
            sf[O_JS + tid] = 0.0f;
        }
        if (tid == 0) sf[O_RED] = 0.0f;
    }
    __syncthreads();

    // colsums S[k] = sum_h w2[h]*W1[h][k]  (reads packed W1 before it is overwritten; ok: overwrite is post-barrier)
    if (tid < 64) {
        const int k = tid;
        const int ub = 4 * (k >> 3) + (k & 3);
        const int ko = (k & 4) ? 2 : 0;
        float ssum = 0.0f;
        #pragma unroll 8
        for (int h = 0; h < Hh; h++) {
            int o = O_WP + h * 128 + ((ub ^ ((h & 1) << 2)) * 4) + ko;
            float v = __uint_as_float(smemu[o]) + __uint_as_float(smemu[o + 1]);
            ssum = fmaf(sf[O_W2 + h], v, ssum);
        }
        sf[O_S + k] = ssum;
    }

    // ---------------- GEMM A: pre[128n x 128h] = XX @ W1[:, :64]^T (3xTF32) ----------------
    const int nblk = (w & 3) * 32;
    const int hblk = (w >> 2) * 64;

    float acc[2][8][4];
    #pragma unroll
    for (int i = 0; i < 2; i++)
        #pragma unroll
        for (int j = 0; j < 8; j++)
            #pragma unroll
            for (int q = 0; q < 4; q++) acc[i][j][q] = 0.0f;

    #pragma unroll 2
    for (int s = 0; s < 8; s++) {
        const int l = s >> 2, g = s & 3;
        // A fragments: row parity = (lr + l) & 1 (nblk, 16i even)
        const int ua = ((4 * g + lc) ^ (((lr + l) & 1) << 2)) * 4;
        const int abase = O_XP + (nblk + lr + l) * 64 + ua;
        uint32_t ah[2][4], al[2][4];
        #pragma unroll
        for (int i = 0; i < 2; i++) {
            uint4 a0 = *(const uint4*)(smemu + abase + i * 1024);
            uint4 a1 = *(const uint4*)(smemu + abase + i * 1024 + 512);
            ah[i][0] = a0.x; al[i][0] = a0.y; ah[i][2] = a0.z; al[i][2] = a0.w;
            ah[i][1] = a1.x; al[i][1] = a1.y; ah[i][3] = a1.z; al[i][3] = a1.w;
        }
        // B fragments: row parity = lr & 1
        const int ub = ((4 * s + lc) ^ ((lr & 1) << 2)) * 4;
        const int bbase = O_WP + (hblk + lr) * 128 + ub;
        #pragma unroll
        for (int j = 0; j < 8; j++) {
            uint4 b = *(const uint4*)(smemu + bbase + j * 1024);
            #pragma unroll
            for (int i = 0; i < 2; i++) {
                mma8(acc[i][j], ah[i], b.x, b.z);
                mma8(acc[i][j], ah[i], b.y, b.w);
                mma8(acc[i][j], al[i], b.x, b.z);
            }
        }
    }

    // ---------------- epilogue A: mask bits, residual + jac[:,64] partials ----------------
    {
        #pragma unroll
        for (int i = 0; i < 2; i++) {
            #pragma unroll
            for (int ci = 0; ci < 2; ci++) {
                const int row = nblk + 16 * i + 8 * ci + lr;
                const float yyv = sf[O_YY + row + 2];
                float rp = 0.0f, jp = 0.0f;
                uint32_t m0 = 0, m1 = 0;
                #pragma unroll
                for (int j = 0; j < 8; j++) {
                    #pragma unroll
                    for (int cj = 0; cj < 2; cj++) {
                        const int h = hblk + 8 * j + 2 * lc + cj;
                        const float wl = sf[O_WLAST + h];
                        float pre = fmaf(yyv, wl, acc[i][j][2 * ci + cj]) + sf[O_B1 + h];
                        float gv = (pre >= 0.0f) ? sf[O_W2 + h] : SLOPE * sf[O_W2 + h];
                        rp = fmaf(pre, gv, rp);
                        jp = fmaf(gv, wl, jp);
                        uint32_t bit = (pre >= 0.0f) ? (1u << (8 * (j & 3) + 2 * lc + cj)) : 0u;
                        if (j < 4) m0 |= bit; else m1 |= bit;
                    }
                }
                m0 |= __shfl_xor_sync(0xffffffffu, m0, 1);
                m0 |= __shfl_xor_sync(0xffffffffu, m0, 2);
                m1 |= __shfl_xor_sync(0xffffffffu, m1, 1);
                m1 |= __shfl_xor_sync(0xffffffffu, m1, 2);
                if (lc == 0) {
                    smemu[O_MASK + row * 4 + (hblk >> 5)]     = m0;
                    smemu[O_MASK + row * 4 + (hblk >> 5) + 1] = m1;
                }
                rp += __shfl_xor_sync(0xffffffffu, rp, 1);
                rp += __shfl_xor_sync(0xffffffffu, rp, 2);
                jp += __shfl_xor_sync(0xffffffffu, jp, 1);
                jp += __shfl_xor_sync(0xffffffffu, jp, 2);
                if (lc == 0) {
                    atomicAdd(&sf[O_RS + row], rp);
                    atomicAdd(&sf[O_JS + row], jp);
                }
            }
        }
    }
    __syncthreads();

    // residual + logdet outputs
    if (tid < 128) {
        const int n = tid;
        out[RES_OFF + ((size_t)(bb * TTt + t0 + n)) * Dd + d] = sf[O_RS + n] + __ldg(&b2[d]);
        float ls = logf(fabsf(sf[O_JS + n]));
        #pragma unroll
        for (int o = 16; o; o >>= 1) ls += __shfl_down_sync(0xffffffffu, ls, o);
        if (lane == 0) atomicAdd(&sf[O_RED], ls);
    }

    // overwrite packed W1 with w2 .* W1 (hi/lo) for GEMM B
    for (int idx = tid; idx < 8192; idx += 256) {
        const int h = idx >> 6, k = idx & 63;
        uint32_t* p = smemu + O_WP + pk_off(h, k, 128);
        float v  = __uint_as_float(p[0]) + __uint_as_float(p[1]);
        float uv = sf[O_W2 + h] * v;
        uint32_t hi, lo;
        split_tf32(uv, hi, lo);
        p[0] = hi; p[1] = lo;
    }
    __syncthreads();

    // ---------------- GEMM B: jac = SLOPE*S + RCOEF*(mask @ (w2.*W1))  (2 terms) ---------
    const int nblk2 = (w & 3) * 32;
    const int kblk  = (w >> 2) * 32;

    float acc2[2][4][4];
    #pragma unroll
    for (int i = 0; i < 2; i++)
        #pragma unroll
        for (int j = 0; j < 4; j++)
            #pragma unroll
            for (int q = 0; q < 4; q++) acc2[i][j][q] = 0.0f;

    // per-thread B column offsets (parity of row 8s+lc is lc&1; +4 keeps parity)
    int boff[4];
    #pragma unroll
    for (int j = 0; j < 4; j++) {
        const int kp = kblk + 8 * j + lr;
        const int u = (4 * (kp >> 3) + (kp & 3)) ^ ((lc & 1) << 2);
        boff[j] = O_WP + u * 4 + ((kp & 4) ? 2 : 0);
    }

    #pragma unroll
    for (int ws = 0; ws < 4; ws++) {
        uint32_t t00 = smemu[O_MASK + (nblk2 + lr) * 4 + ws] >> lc;
        uint32_t t01 = smemu[O_MASK + (nblk2 + lr + 8) * 4 + ws] >> lc;
        uint32_t t10 = smemu[O_MASK + (nblk2 + 16 + lr) * 4 + ws] >> lc;
        uint32_t t11 = smemu[O_MASK + (nblk2 + 16 + lr + 8) * 4 + ws] >> lc;
        #pragma unroll
        for (int ss = 0; ss < 4; ss++) {
            const int s = 4 * ws + ss;
            uint32_t a[2][4];
            a[0][0] = ((t00 >> (8 * ss)) & 1u) * 0x3F800000u;
            a[0][1] = ((t01 >> (8 * ss)) & 1u) * 0x3F800000u;
            a[0][2] = ((t00 >> (8 * ss + 4)) & 1u) * 0x3F800000u;
            a[0][3] = ((t01 >> (8 * ss + 4)) & 1u) * 0x3F800000u;
            a[1][0] = ((t10 >> (8 * ss)) & 1u) * 0x3F800000u;
            a[1][1] = ((t11 >> (8 * ss)) & 1u) * 0x3F800000u;
            a[1][2] = ((t10 >> (8 * ss + 4)) & 1u) * 0x3F800000u;
            a[1][3] = ((t11 >> (8 * ss + 4)) & 1u) * 0x3F800000u;
            const int rA = (8 * s + lc) * 128;
            const int rB = (8 * s + lc + 4) * 128;
            #pragma unroll
            for (int j = 0; j < 4; j++) {
                uint2 bA = *(const uint2*)(smemu + boff[j] + rA);  // (hi, lo) at row 8s+lc
                uint2 bB = *(const uint2*)(smemu + boff[j] + rB);  // (hi, lo) at row 8s+lc+4
                #pragma unroll
                for (int i = 0; i < 2; i++) {
                    mma8(acc2[i][j], a[i], bA.x, bB.x);
                    mma8(acc2[i][j], a[i], bA.y, bB.y);
                }
            }
        }
    }

    // write hist_jac: jac = SLOPE*S[k] + RCOEF*acc2
    #pragma unroll
    for (int i = 0; i < 2; i++) {
        #pragma unroll
        for (int ci = 0; ci < 2; ci++) {
            const int r = nblk2 + 16 * i + 8 * ci + lr;
            float* hb = out + HIST_OFF + ((size_t)d * NTOT + n0 + r) * 64;
            #pragma unroll
            for (int j = 0; j < 4; j++) {
                const int col = kblk + 8 * j + 2 * lc;
                const float s0 = sf[O_S + col];
                const float s1 = sf[O_S + col + 1];
                float2 v = make_float2(fmaf(RCOEF, acc2[i][j][2 * ci],     SLOPE * s0),
                                       fmaf(RCOEF, acc2[i][j][2 * ci + 1], SLOPE * s1));
                *(float2*)(hb + col) = v;
            }
        }
    }

    __syncthreads();
    if (tid == 0) atomicAdd(&out[SUM_OFF + bb], sf[O_RED]);
}

extern "C" void kernel_launch(void* const* d_in, const int* in_sizes, int n_in,
                              void* d_out, int out_size) {
    const float* x  = (const float*)d_in[0];
    const float* W1 = (const float*)d_in[1];
    const float* b1 = (const float*)d_in[2];
    const float* W2 = (const float*)d_in[3];
    const float* b2 = (const float*)d_in[4];
    float* out = (float*)d_out;

    cudaFuncSetAttribute(fused_mma, cudaFuncAttributeMaxDynamicSharedMemorySize, SMEM_BYTES);

    zero_sum_kernel<<<1, Bb>>>(out);
    fused_mma<<<dim3(Dd, NTILES), 256, SMEM_BYTES>>>(x, W1, b1, W2, b2, out);
}

// round 8
// speedup vs baseline: 1.1513x; 1.1513x over previous
#include <cuda_runtime.h>
#include <math.h>
#include <stdint.h>

#define SLOPE 0.01f
constexpr float RCOEF = 1.0f - SLOPE;

// -------- problem constants --------
constexpr int Dd    = 32;
constexpr int Hh    = 128;
constexpr int Bb    = 64;
constexpr int Tt    = 514;
constexpr int TTt   = 512;
constexpr int NTOT  = Bb * TTt;          // 32768
constexpr int NTILE = 128;
constexpr int NTILES = NTOT / NTILE;     // 256

// output layout (reference return order, concatenated)
constexpr size_t RES_OFF  = 0;                        // (64,512,32)
constexpr size_t SUM_OFF  = (size_t)Bb * TTt * Dd;    // (64,)
constexpr size_t HIST_OFF = SUM_OFF + Bb;             // (32,32768,1,64)

// -------- shared offsets (u32 units) --------
constexpr int XWS = 36;                  // x-window row stride (fp32)
constexpr int W1S = 72;                  // W1 hi/lo row stride (64 used, pair-interleaved)
constexpr int O_XW    = 0;                               // 130*36 = 4680
constexpr int O_W1H   = 4680;                            // 128*72 = 9216
constexpr int O_W1L   = 13896;                           // 9216
constexpr int O_MASK  = 23112;                           // 128*4
constexpr int O_S     = 23624;                           // 64
constexpr int O_WLAST = 23688;                           // 128
constexpr int O_B1    = 23816;                           // 128
constexpr int O_W2    = 23944;                           // 128
constexpr int O_YY    = 24072;                           // 132
constexpr int O_RS    = 24204;                           // 128
constexpr int O_JS    = 24332;                           // 128
constexpr int O_RED   = 24460;                           // 4
constexpr int SMEM_U32 = 24464;
constexpr int SMEM_BYTES = SMEM_U32 * 4;                 // 97856

__device__ __forceinline__ uint32_t f2tf32(float f) {
    uint32_t u;
    asm("cvt.rna.tf32.f32 %0, %1;" : "=r"(u) : "f"(f));
    return u;
}
__device__ __forceinline__ void split_tf32(float v, uint32_t& hi, uint32_t& lo) {
    hi = f2tf32(v);
    lo = f2tf32(v - __uint_as_float(hi));
}
// pair-interleaved column position within a row: chunks of 8, order [k,k+4,k+1,k+5,k+2,k+6,k+3,k+7]
__device__ __forceinline__ int kperm(int k) {
    return (k & ~7) + 2 * (k & 3) + ((k >> 2) & 1);
}

__device__ __forceinline__ void mma8(float* d, const uint32_t* a, uint32_t b0, uint32_t b1) {
    asm volatile(
        "mma.sync.aligned.m16n8k8.row.col.f32.tf32.tf32.f32 "
        "{%0,%1,%2,%3}, {%4,%5,%6,%7}, {%8,%9}, {%0,%1,%2,%3};"
        : "+f"(d[0]), "+f"(d[1]), "+f"(d[2]), "+f"(d[3])
        : "r"(a[0]), "r"(a[1]), "r"(a[2]), "r"(a[3]), "r"(b0), "r"(b1));
}

__global__ void zero_sum_kernel(float* out) { out[SUM_OFF + threadIdx.x] = 0.0f; }

extern __shared__ uint32_t smemu[];

__global__ __launch_bounds__(256, 2)
void fused_mma(const float* __restrict__ x,  const float* __restrict__ W1,
               const float* __restrict__ b1, const float* __restrict__ W2,
               const float* __restrict__ b2, float* __restrict__ out)
{
    float* sf = (float*)smemu;
    const int tid  = threadIdx.x;
    const int lane = tid & 31;
    const int w    = tid >> 5;
    const int lr   = lane >> 2;   // 0..7
    const int lc   = lane & 3;    // 0..3

    const int d  = blockIdx.x;
    const int n0 = blockIdx.y * NTILE;
    const int bb = n0 / TTt;
    const int t0 = n0 % TTt;

    // ---------------- preamble ----------------
    {
        const float* W1g = W1 + (size_t)d * Hh * 65;
        for (int idx = tid; idx < Hh * 65; idx += 256) {
            int h = idx / 65;
            int k = idx - h * 65;
            float v = W1g[idx];
            if (k == 64) sf[O_WLAST + h] = v;
            else {
                uint32_t hi, lo;
                split_tf32(v, hi, lo);
                int o = h * W1S + kperm(k);
                smemu[O_W1H + o] = hi;
                smemu[O_W1L + o] = lo;
            }
        }
        const float* xg = x + ((size_t)bb * Tt + t0) * Dd;
        for (int idx = tid; idx < 130 * 32; idx += 256) {
            int r = idx >> 5, c = idx & 31;
            float v = xg[idx];
            sf[O_XW + r * XWS + c] = v;
            if (c == d) sf[O_YY + r] = v;
        }
        if (tid < 128) {
            sf[O_B1 + tid] = b1[(size_t)d * Hh + tid];
            sf[O_W2 + tid] = W2[(size_t)d * Hh + tid];
            sf[O_RS + tid] = 0.0f;
            sf[O_JS + tid] = 0.0f;
        }
        if (tid == 0) sf[O_RED] = 0.0f;
    }
    __syncthreads();

    // colsums S[k] = sum_h w2[h]*W1[h][k]  (pre-overwrite values; same barrier side as GEMM A)
    if (tid < 64) {
        const int kw = kperm(tid);
        float ssum = 0.0f;
        #pragma unroll 8
        for (int h = 0; h < Hh; h++) {
            float v = __uint_as_float(smemu[O_W1H + h * W1S + kw]) +
                      __uint_as_float(smemu[O_W1L + h * W1S + kw]);
            ssum = fmaf(sf[O_W2 + h], v, ssum);
        }
        sf[O_S + tid] = ssum;
    }

    // ---------------- GEMM A: pre[128n x 128h] = XX @ W1[:, :64]^T (3xTF32) ----------------
    const int nblk = (w & 3) * 32;
    const int hblk = (w >> 2) * 64;

    float acc[2][8][4];
    #pragma unroll
    for (int i = 0; i < 2; i++)
        #pragma unroll
        for (int j = 0; j < 8; j++)
            #pragma unroll
            for (int q = 0; q < 4; q++) acc[i][j][q] = 0.0f;

    #pragma unroll 2
    for (int s = 0; s < 8; s++) {
        const int l  = s >> 2;
        const int c0 = ((8 * s) & 31) + lc;
        // A fragments: fp32 x -> split in registers (amortized over 8 j)
        uint32_t ah[2][4], al[2][4];
        #pragma unroll
        for (int i = 0; i < 2; i++) {
            int base = O_XW + (nblk + 16 * i + lr + l) * XWS + c0;
            split_tf32(sf[base],               ah[i][0], al[i][0]);
            split_tf32(sf[base + 8 * XWS],     ah[i][1], al[i][1]);
            split_tf32(sf[base + 4],           ah[i][2], al[i][2]);
            split_tf32(sf[base + 8 * XWS + 4], ah[i][3], al[i][3]);
        }
        // B fragments: precomputed hi/lo, pair-interleaved -> LDS.64 each
        const int bw = 8 * s + 2 * lc;
        #pragma unroll
        for (int j = 0; j < 8; j++) {
            const int rw = (hblk + 8 * j + lr) * W1S + bw;
            uint2 bh = *(const uint2*)(smemu + O_W1H + rw);   // (k=8s+lc, k=8s+lc+4)
            uint2 bl = *(const uint2*)(smemu + O_W1L + rw);
            #pragma unroll
            for (int i = 0; i < 2; i++) {
                mma8(acc[i][j], ah[i], bh.x, bh.y);
                mma8(acc[i][j], ah[i], bl.x, bl.y);
                mma8(acc[i][j], al[i], bh.x, bh.y);
            }
        }
    }

    // ---------------- epilogue A: mask bits, residual + jac[:,64] partials ----------------
    {
        #pragma unroll
        for (int i = 0; i < 2; i++) {
            #pragma unroll
            for (int ci = 0; ci < 2; ci++) {
                const int row = nblk + 16 * i + 8 * ci + lr;
                const float yyv = sf[O_YY + row + 2];
                float rp = 0.0f, jp = 0.0f;
                uint32_t m0 = 0, m1 = 0;
                #pragma unroll
                for (int j = 0; j < 8; j++) {
                    #pragma unroll
                    for (int cj = 0; cj < 2; cj++) {
                        const int h = hblk + 8 * j + 2 * lc + cj;
                        const float wl = sf[O_WLAST + h];
                        float pre = fmaf(yyv, wl, acc[i][j][2 * ci + cj]) + sf[O_B1 + h];
                        float gv = (pre >= 0.0f) ? sf[O_W2 + h] : SLOPE * sf[O_W2 + h];
                        rp = fmaf(pre, gv, rp);
                        jp = fmaf(gv, wl, jp);
                        uint32_t bit = (pre >= 0.0f) ? (1u << (8 * (j & 3) + 2 * lc + cj)) : 0u;
                        if (j < 4) m0 |= bit; else m1 |= bit;
                    }
                }
                m0 |= __shfl_xor_sync(0xffffffffu, m0, 1);
                m0 |= __shfl_xor_sync(0xffffffffu, m0, 2);
                m1 |= __shfl_xor_sync(0xffffffffu, m1, 1);
                m1 |= __shfl_xor_sync(0xffffffffu, m1, 2);
                if (lc == 0) {
                    smemu[O_MASK + row * 4 + (hblk >> 5)]     = m0;
                    smemu[O_MASK + row * 4 + (hblk >> 5) + 1] = m1;
                }
                rp += __shfl_xor_sync(0xffffffffu, rp, 1);
                rp += __shfl_xor_sync(0xffffffffu, rp, 2);
                jp += __shfl_xor_sync(0xffffffffu, jp, 1);
                jp += __shfl_xor_sync(0xffffffffu, jp, 2);
                if (lc == 0) {
                    atomicAdd(&sf[O_RS + row], rp);
                    atomicAdd(&sf[O_JS + row], jp);
                }
            }
        }
    }
    __syncthreads();

    // residual + logdet outputs
    if (tid < 128) {
        const int n = tid;
        out[RES_OFF + ((size_t)(bb * TTt + t0 + n)) * Dd + d] = sf[O_RS + n] + __ldg(&b2[d]);
        float ls = logf(fabsf(sf[O_JS + n]));
        #pragma unroll
        for (int o = 16; o; o >>= 1) ls += __shfl_down_sync(0xffffffffu, ls, o);
        if (lane == 0) atomicAdd(&sf[O_RED], ls);
    }

    // overwrite W1 hi/lo in place with w2 .* W1 (elementwise; position permutation irrelevant)
    for (int idx = tid; idx < Hh * 64; idx += 256) {
        const int h = idx >> 6, p = idx & 63;
        uint32_t* ph = smemu + O_W1H + h * W1S + p;
        uint32_t* pl = smemu + O_W1L + h * W1S + p;
        float v  = __uint_as_float(*ph) + __uint_as_float(*pl);
        float uv = sf[O_W2 + h] * v;
        uint32_t hi, lo;
        split_tf32(uv, hi, lo);
        *ph = hi; *pl = lo;
    }
    __syncthreads();

    // ---------------- GEMM B: jac = SLOPE*S + RCOEF*(mask @ (w2.*W1))  (exact A, 2-term B) --
    const int nblk2 = (w & 3) * 32;
    const int kblk  = (w >> 2) * 32;

    uint32_t mA[2][4], mB[2][4];
    #pragma unroll
    for (int i = 0; i < 2; i++) {
        const int r1 = nblk2 + 16 * i + lr;
        #pragma unroll
        for (int q = 0; q < 4; q++) {
            mA[i][q] = smemu[O_MASK + r1 * 4 + q];
            mB[i][q] = smemu[O_MASK + (r1 + 8) * 4 + q];
        }
    }

    // per-thread B column word (permuted position of kp = kblk + 8j + lr)
    int kcol[4];
    #pragma unroll
    for (int j = 0; j < 4; j++)
        kcol[j] = kblk + 8 * j + 2 * (lr & 3) + (lr >> 2);

    float acc2[2][4][4];
    #pragma unroll
    for (int i = 0; i < 2; i++)
        #pragma unroll
        for (int j = 0; j < 4; j++)
            #pragma unroll
            for (int q = 0; q < 4; q++) acc2[i][j][q] = 0.0f;

    #pragma unroll
    for (int ws = 0; ws < 4; ws++) {
        uint32_t t00 = mA[0][ws] >> lc;
        uint32_t t01 = mB[0][ws] >> lc;
        uint32_t t10 = mA[1][ws] >> lc;
        uint32_t t11 = mB[1][ws] >> lc;
        #pragma unroll
        for (int ss = 0; ss < 4; ss++) {
            const int s = 4 * ws + ss;
            uint32_t a[2][4];
            a[0][0] = ((t00 >> (8 * ss)) & 1u) * 0x3F800000u;
            a[0][1] = ((t01 >> (8 * ss)) & 1u) * 0x3F800000u;
            a[0][2] = ((t00 >> (8 * ss + 4)) & 1u) * 0x3F800000u;
            a[0][3] = ((t01 >> (8 * ss + 4)) & 1u) * 0x3F800000u;
            a[1][0] = ((t10 >> (8 * ss)) & 1u) * 0x3F800000u;
            a[1][1] = ((t11 >> (8 * ss)) & 1u) * 0x3F800000u;
            a[1][2] = ((t10 >> (8 * ss + 4)) & 1u) * 0x3F800000u;
            a[1][3] = ((t11 >> (8 * ss + 4)) & 1u) * 0x3F800000u;
            const int r0 = (8 * s + lc) * W1S;
            const int r1 = (8 * s + lc + 4) * W1S;
            #pragma unroll
            for (int j = 0; j < 4; j++) {
                uint32_t bh0 = smemu[O_W1H + r0 + kcol[j]];
                uint32_t bh1 = smemu[O_W1H + r1 + kcol[j]];
                uint32_t bl0 = smemu[O_W1L + r0 + kcol[j]];
                uint32_t bl1 = smemu[O_W1L + r1 + kcol[j]];
                #pragma unroll
                for (int i = 0; i < 2; i++) {
                    mma8(acc2[i][j], a[i], bh0, bh1);
                    mma8(acc2[i][j], a[i], bl0, bl1);
                }
            }
        }
    }

    // write hist_jac: jac = SLOPE*S[k] + RCOEF*acc2
    #pragma unroll
    for (int i = 0; i < 2; i++) {
        #pragma unroll
        for (int ci = 0; ci < 2; ci++) {
            const int r = nblk2 + 16 * i + 8 * ci + lr;
            float* hb = out + HIST_OFF + ((size_t)d * NTOT + n0 + r) * 64;
            #pragma unroll
            for (int j = 0; j < 4; j++) {
                const int col = kblk + 8 * j + 2 * lc;
                const float s0 = sf[O_S + col];
                const float s1 = sf[O_S + col + 1];
                float2 v = make_float2(fmaf(RCOEF, acc2[i][j][2 * ci],     SLOPE * s0),
                                       fmaf(RCOEF, acc2[i][j][2 * ci + 1], SLOPE * s1));
                *(float2*)(hb + col) = v;
            }
        }
    }

    __syncthreads();
    if (tid == 0) atomicAdd(&out[SUM_OFF + bb], sf[O_RED]);
}

extern "C" void kernel_launch(void* const* d_in, const int* in_sizes, int n_in,
                              void* d_out, int out_size) {
    const float* x  = (const float*)d_in[0];
    const float* W1 = (const float*)d_in[1];
    const float* b1 = (const float*)d_in[2];
    const float* W2 = (const float*)d_in[3];
    const float* b2 = (const float*)d_in[4];
    float* out = (float*)d_out;

    cudaFuncSetAttribute(fused_mma, cudaFuncAttributeMaxDynamicSharedMemorySize, SMEM_BYTES);

    zero_sum_kernel<<<1, Bb>>>(out);
    fused_mma<<<dim3(Dd, NTILES), 256, SMEM_BYTES>>>(x, W1, b1, W2, b2, out);
}

// round 9
// speedup vs baseline: 1.2830x; 1.1144x over previous
#include <cuda_runtime.h>
#include <math.h>
#include <stdint.h>

#define SLOPE 0.01f
constexpr float RCOEF = 1.0f - SLOPE;

// -------- problem constants --------
constexpr int Dd    = 32;
constexpr int Hh    = 128;
constexpr int Bb    = 64;
constexpr int Tt    = 514;
constexpr int TTt   = 512;
constexpr int NTOT  = Bb * TTt;          // 32768
constexpr int NTILE = 128;
constexpr int NTILES = NTOT / NTILE;     // 256

// output layout (reference return order, concatenated)
constexpr size_t RES_OFF  = 0;                        // (64,512,32)
constexpr size_t SUM_OFF  = (size_t)Bb * TTt * Dd;    // (64,)
constexpr size_t HIST_OFF = SUM_OFF + Bb;             // (32,32768,1,64)

// -------- shared offsets (u32 units) — identical to R5 (59 KB, fits 3 CTAs/SM) --------
constexpr int XWS = 36;                  // x-window row stride
constexpr int W1S = 68;                  // W1 row stride
constexpr int O_XW    = 0;                               // 130*36 = 4680
constexpr int O_W1    = 4680;                            // 128*68 = 8704
constexpr int O_MASK  = 13384;                           // 128*4
constexpr int O_S     = 13896;                           // 64
constexpr int O_WLAST = 13960;                           // 128
constexpr int O_B1    = 14088;                           // 128
constexpr int O_W2    = 14216;                           // 128
constexpr int O_YY    = 14344;                           // 132
constexpr int O_RS    = 14476;                           // 128
constexpr int O_JS    = 14604;                           // 128
constexpr int O_RED   = 14732;                           // 4
constexpr int SMEM_U32 = 14736;
constexpr int SMEM_BYTES = SMEM_U32 * 4;                 // 58944

__device__ __forceinline__ uint32_t f2tf32(float f) {
    uint32_t u;
    asm("cvt.rna.tf32.f32 %0, %1;" : "=r"(u) : "f"(f));
    return u;
}
__device__ __forceinline__ void split_tf32(float v, uint32_t& hi, uint32_t& lo) {
    hi = f2tf32(v);
    lo = f2tf32(v - __uint_as_float(hi));
}

__device__ __forceinline__ void mma8(float* d, const uint32_t* a, uint32_t b0, uint32_t b1) {
    asm volatile(
        "mma.sync.aligned.m16n8k8.row.col.f32.tf32.tf32.f32 "
        "{%0,%1,%2,%3}, {%4,%5,%6,%7}, {%8,%9}, {%0,%1,%2,%3};"
        : "+f"(d[0]), "+f"(d[1]), "+f"(d[2]), "+f"(d[3])
        : "r"(a[0]), "r"(a[1]), "r"(a[2]), "r"(a[3]), "r"(b0), "r"(b1));
}

__global__ void zero_sum_kernel(float* out) { out[SUM_OFF + threadIdx.x] = 0.0f; }

extern __shared__ uint32_t smemu[];

__global__ __launch_bounds__(256, 3)
void fused_mma(const float* __restrict__ x,  const float* __restrict__ W1,
               const float* __restrict__ b1, const float* __restrict__ W2,
               const float* __restrict__ b2, float* __restrict__ out)
{
    float* sf = (float*)smemu;
    const int tid  = threadIdx.x;
    const int lane = tid & 31;
    const int w    = tid >> 5;
    const int lr   = lane >> 2;   // 0..7
    const int lc   = lane & 3;    // 0..3

    const int d  = blockIdx.x;
    const int n0 = blockIdx.y * NTILE;
    const int bb = n0 / TTt;
    const int t0 = n0 % TTt;

    // ---------------- preamble (R5) ----------------
    {
        const float* W1g = W1 + (size_t)d * Hh * 65;
        for (int idx = tid; idx < Hh * 65; idx += 256) {
            int h = idx / 65;
            int k = idx - h * 65;
            float v = W1g[idx];
            if (k == 64) sf[O_WLAST + h] = v;
            else         sf[O_W1 + h * W1S + k] = v;
        }
        const float* xg = x + ((size_t)bb * Tt + t0) * Dd;
        for (int idx = tid; idx < 130 * 32; idx += 256) {
            int r = idx >> 5, c = idx & 31;
            float v = xg[idx];
            sf[O_XW + r * XWS + c] = v;
            if (c == d) sf[O_YY + r] = v;
        }
        if (tid < 128) {
            sf[O_B1 + tid] = b1[(size_t)d * Hh + tid];
            sf[O_W2 + tid] = W2[(size_t)d * Hh + tid];
            sf[O_RS + tid] = 0.0f;
            sf[O_JS + tid] = 0.0f;
        }
        if (tid == 0) sf[O_RED] = 0.0f;
    }
    __syncthreads();

    // colsums S[k] = sum_h w2[h]*W1[h][k]
    if (tid < 64) {
        float s = 0.0f;
        #pragma unroll 8
        for (int h = 0; h < Hh; h++)
            s = fmaf(sf[O_W2 + h], sf[O_W1 + h * W1S + tid], s);
        sf[O_S + tid] = s;
    }

    // ---------------- GEMM A: pre = XX @ W1[:, :64]^T (3xTF32), two 16-row passes --------
    const int nblk = (w & 3) * 32;
    const int hblk = (w >> 2) * 64;

    #pragma unroll 1
    for (int pass = 0; pass < 2; pass++) {
        const int rbase = nblk + 16 * pass;

        float acc[8][4];
        #pragma unroll
        for (int j = 0; j < 8; j++)
            #pragma unroll
            for (int q = 0; q < 4; q++) acc[j][q] = 0.0f;

        #pragma unroll 2
        for (int s = 0; s < 8; s++) {
            const int l  = s >> 2;
            const int c0 = ((8 * s) & 31) + lc;
            uint32_t ah[4], al[4];
            {
                int base = O_XW + (rbase + lr + l) * XWS + c0;
                split_tf32(sf[base],               ah[0], al[0]);
                split_tf32(sf[base + 8 * XWS],     ah[1], al[1]);
                split_tf32(sf[base + 4],           ah[2], al[2]);
                split_tf32(sf[base + 8 * XWS + 4], ah[3], al[3]);
            }
            #pragma unroll
            for (int j = 0; j < 8; j++) {
                int hb = O_W1 + (hblk + 8 * j + lr) * W1S + 8 * s + lc;
                uint32_t bh0, bl0, bh1, bl1;
                split_tf32(sf[hb],     bh0, bl0);
                split_tf32(sf[hb + 4], bh1, bl1);
                mma8(acc[j], ah, bh0, bh1);
                mma8(acc[j], ah, bl0, bl1);
                mma8(acc[j], al, bh0, bh1);
            }
        }

        // epilogue for this pass: rows rbase + 8*ci + lr
        #pragma unroll
        for (int ci = 0; ci < 2; ci++) {
            const int row = rbase + 8 * ci + lr;
            const float yyv = sf[O_YY + row + 2];
            float rp = 0.0f, jp = 0.0f;
            uint32_t m0 = 0, m1 = 0;
            #pragma unroll
            for (int j = 0; j < 8; j++) {
                #pragma unroll
                for (int cj = 0; cj < 2; cj++) {
                    const int h = hblk + 8 * j + 2 * lc + cj;
                    const float wl = sf[O_WLAST + h];
                    float pre = fmaf(yyv, wl, acc[j][2 * ci + cj]) + sf[O_B1 + h];
                    float gv = (pre >= 0.0f) ? sf[O_W2 + h] : SLOPE * sf[O_W2 + h];
                    rp = fmaf(pre, gv, rp);
                    jp = fmaf(gv, wl, jp);
                    uint32_t bit = (pre >= 0.0f) ? (1u << (8 * (j & 3) + 2 * lc + cj)) : 0u;
                    if (j < 4) m0 |= bit; else m1 |= bit;
                }
            }
            m0 |= __shfl_xor_sync(0xffffffffu, m0, 1);
            m0 |= __shfl_xor_sync(0xffffffffu, m0, 2);
            m1 |= __shfl_xor_sync(0xffffffffu, m1, 1);
            m1 |= __shfl_xor_sync(0xffffffffu, m1, 2);
            if (lc == 0) {
                smemu[O_MASK + row * 4 + (hblk >> 5)]     = m0;
                smemu[O_MASK + row * 4 + (hblk >> 5) + 1] = m1;
            }
            rp += __shfl_xor_sync(0xffffffffu, rp, 1);
            rp += __shfl_xor_sync(0xffffffffu, rp, 2);
            jp += __shfl_xor_sync(0xffffffffu, jp, 1);
            jp += __shfl_xor_sync(0xffffffffu, jp, 2);
            if (lc == 0) {
                atomicAdd(&sf[O_RS + row], rp);
                atomicAdd(&sf[O_JS + row], jp);
            }
        }
    }
    __syncthreads();

    // residual + logdet outputs
    if (tid < 128) {
        const int n = tid;
        out[RES_OFF + ((size_t)(bb * TTt + t0 + n)) * Dd + d] = sf[O_RS + n] + __ldg(&b2[d]);
        float ls = logf(fabsf(sf[O_JS + n]));
        #pragma unroll
        for (int o = 16; o; o >>= 1) ls += __shfl_down_sync(0xffffffffu, ls, o);
        if (lane == 0) atomicAdd(&sf[O_RED], ls);
    }

    // ---------------- GEMM B: jac = SLOPE*S + RCOEF*(mask @ (w2.*W1)) (R5 math) ----------
    const int nblk2 = (w & 3) * 32;
    const int kblk  = (w >> 2) * 32;

    float acc2[2][4][4];
    #pragma unroll
    for (int i = 0; i < 2; i++)
        #pragma unroll
        for (int j = 0; j < 4; j++)
            #pragma unroll
            for (int q = 0; q < 4; q++) acc2[i][j][q] = 0.0f;

    #pragma unroll 1
    for (int ws = 0; ws < 4; ws++) {
        // re-read masks per ws to keep register pressure low
        uint32_t t00 = smemu[O_MASK + (nblk2 + lr) * 4 + ws] >> lc;
        uint32_t t01 = smemu[O_MASK + (nblk2 + lr + 8) * 4 + ws] >> lc;
        uint32_t t10 = smemu[O_MASK + (nblk2 + 16 + lr) * 4 + ws] >> lc;
        uint32_t t11 = smemu[O_MASK + (nblk2 + 16 + lr + 8) * 4 + ws] >> lc;
        #pragma unroll
        for (int ss = 0; ss < 4; ss++) {
            const int s = 4 * ws + ss;
            uint32_t a[2][4];
            a[0][0] = ((t00 >> (8 * ss)) & 1u) * 0x3F800000u;
            a[0][1] = ((t01 >> (8 * ss)) & 1u) * 0x3F800000u;
            a[0][2] = ((t00 >> (8 * ss + 4)) & 1u) * 0x3F800000u;
            a[0][3] = ((t01 >> (8 * ss + 4)) & 1u) * 0x3F800000u;
            a[1][0] = ((t10 >> (8 * ss)) & 1u) * 0x3F800000u;
            a[1][1] = ((t11 >> (8 * ss)) & 1u) * 0x3F800000u;
            a[1][2] = ((t10 >> (8 * ss + 4)) & 1u) * 0x3F800000u;
            a[1][3] = ((t11 >> (8 * ss + 4)) & 1u) * 0x3F800000u;
            const float w2a = sf[O_W2 + 8 * s + lc];
            const float w2b = sf[O_W2 + 8 * s + lc + 4];
            #pragma unroll
            for (int j = 0; j < 4; j++) {
                const int kp = kblk + 8 * j + lr;
                float u0 = sf[O_W1 + (8 * s + lc) * W1S + kp] * w2a;
                float u1 = sf[O_W1 + (8 * s + lc + 4) * W1S + kp] * w2b;
                uint32_t bh0, bl0, bh1, bl1;
                split_tf32(u0, bh0, bl0);
                split_tf32(u1, bh1, bl1);
                #pragma unroll
                for (int i = 0; i < 2; i++) {
                    mma8(acc2[i][j], a[i], bh0, bh1);
                    mma8(acc2[i][j], a[i], bl0, bl1);
                }
            }
        }
    }

    // write hist_jac: jac = SLOPE*S[k] + RCOEF*acc2
    #pragma unroll
    for (int i = 0; i < 2; i++) {
        #pragma unroll
        for (int ci = 0; ci < 2; ci++) {
            const int r = nblk2 + 16 * i + 8 * ci + lr;
            float* hb = out + HIST_OFF + ((size_t)d * NTOT + n0 + r) * 64;
            #pragma unroll
            for (int j = 0; j < 4; j++) {
                const int col = kblk + 8 * j + 2 * lc;
                const float s0 = sf[O_S + col];
                const float s1 = sf[O_S + col + 1];
                float2 v = make_float2(fmaf(RCOEF, acc2[i][j][2 * ci],     SLOPE * s0),
                                       fmaf(RCOEF, acc2[i][j][2 * ci + 1], SLOPE * s1));
                *(float2*)(hb + col) = v;
            }
        }
    }

    __syncthreads();
    if (tid == 0) atomicAdd(&out[SUM_OFF + bb], sf[O_RED]);
}

extern "C" void kernel_launch(void* const* d_in, const int* in_sizes, int n_in,
                              void* d_out, int out_size) {
    const float* x  = (const float*)d_in[0];
    const float* W1 = (const float*)d_in[1];
    const float* b1 = (const float*)d_in[2];
    const float* W2 = (const float*)d_in[3];
    const float* b2 = (const float*)d_in[4];
    float* out = (float*)d_out;

    cudaFuncSetAttribute(fused_mma, cudaFuncAttributeMaxDynamicSharedMemorySize, SMEM_BYTES);

    zero_sum_kernel<<<1, Bb>>>(out);
    fused_mma<<<dim3(Dd, NTILES), 256, SMEM_BYTES>>>(x, W1, b1, W2, b2, out);
}

// round 10
// speedup vs baseline: 1.5581x; 1.2144x over previous
#include <cuda_runtime.h>
#include <math.h>
#include <stdint.h>

#define SLOPE 0.01f
constexpr float RCOEF = 1.0f - SLOPE;

// -------- problem constants --------
constexpr int Dd    = 32;
constexpr int Hh    = 128;
constexpr int Bb    = 64;
constexpr int Tt    = 514;
constexpr int TTt   = 512;
constexpr int NTOT  = Bb * TTt;          // 32768
constexpr int NTILE = 128;
constexpr int NTILES = NTOT / NTILE;     // 256

// output layout (reference return order, concatenated)
constexpr size_t RES_OFF  = 0;                        // (64,512,32)
constexpr size_t SUM_OFF  = (size_t)Bb * TTt * Dd;    // (64,)
constexpr size_t HIST_OFF = SUM_OFF + Bb;             // (32,32768,1,64)

// -------- shared offsets (u32 units) — 59 KB, 3 CTAs/SM --------
constexpr int XWS = 36;                  // x-window row stride
constexpr int W1S = 68;                  // W1 row stride
constexpr int O_XW    = 0;                               // 130*36 = 4680
constexpr int O_W1    = 4680;                            // 128*68 = 8704
constexpr int O_MASK  = 13384;                           // 128*4
constexpr int O_S     = 13896;                           // 64
constexpr int O_WLAST = 13960;                           // 128
constexpr int O_B1    = 14088;                           // 128
constexpr int O_W2    = 14216;                           // 128
constexpr int O_YY    = 14344;                           // 132
constexpr int O_RS    = 14476;                           // 128
constexpr int O_JS    = 14604;                           // 128
constexpr int O_RED   = 14732;                           // 4
constexpr int SMEM_U32 = 14736;
constexpr int SMEM_BYTES = SMEM_U32 * 4;                 // 58944

// CUTLASS-style fast 3xTF32 split: hi = truncate-to-tf32 (LOP3), lo = exact tail (FADD).
// lo is passed raw: tf32 HMMA reads only the top 19 bits, truncating for us.
__device__ __forceinline__ void split_fast(float v, uint32_t& hi, uint32_t& lo) {
    hi = __float_as_uint(v) & 0xFFFFE000u;
    lo = __float_as_uint(v - __uint_as_float(hi));
}

__device__ __forceinline__ void mma8(float* d, const uint32_t* a, uint32_t b0, uint32_t b1) {
    asm volatile(
        "mma.sync.aligned.m16n8k8.row.col.f32.tf32.tf32.f32 "
        "{%0,%1,%2,%3}, {%4,%5,%6,%7}, {%8,%9}, {%0,%1,%2,%3};"
        : "+f"(d[0]), "+f"(d[1]), "+f"(d[2]), "+f"(d[3])
        : "r"(a[0]), "r"(a[1]), "r"(a[2]), "r"(a[3]), "r"(b0), "r"(b1));
}

__global__ void zero_sum_kernel(float* out) { out[SUM_OFF + threadIdx.x] = 0.0f; }

extern __shared__ uint32_t smemu[];

__global__ __launch_bounds__(256, 3)
void fused_mma(const float* __restrict__ x,  const float* __restrict__ W1,
               const float* __restrict__ b1, const float* __restrict__ W2,
               const float* __restrict__ b2, float* __restrict__ out)
{
    float* sf = (float*)smemu;
    const int tid  = threadIdx.x;
    const int lane = tid & 31;
    const int w    = tid >> 5;
    const int lr   = lane >> 2;   // 0..7
    const int lc   = lane & 3;    // 0..3

    const int d  = blockIdx.x;
    const int n0 = blockIdx.y * NTILE;
    const int bb = n0 / TTt;
    const int t0 = n0 % TTt;

    // ---------------- preamble ----------------
    {
        const float* W1g = W1 + (size_t)d * Hh * 65;
        for (int idx = tid; idx < Hh * 65; idx += 256) {
            int h = idx / 65;
            int k = idx - h * 65;
            float v = W1g[idx];
            if (k == 64) sf[O_WLAST + h] = v;
            else         sf[O_W1 + h * W1S + k] = v;
        }
        const float* xg = x + ((size_t)bb * Tt + t0) * Dd;
        for (int idx = tid; idx < 130 * 32; idx += 256) {
            int r = idx >> 5, c = idx & 31;
            float v = xg[idx];
            sf[O_XW + r * XWS + c] = v;
            if (c == d) sf[O_YY + r] = v;
        }
        if (tid < 128) {
            sf[O_B1 + tid] = b1[(size_t)d * Hh + tid];
            sf[O_W2 + tid] = W2[(size_t)d * Hh + tid];
            sf[O_RS + tid] = 0.0f;
            sf[O_JS + tid] = 0.0f;
        }
        if (tid == 0) sf[O_RED] = 0.0f;
    }
    __syncthreads();

    // colsums S[k] = sum_h w2[h]*W1[h][k]  (original W1; consumed after post-epilogue barrier)
    if (tid < 64) {
        float s = 0.0f;
        #pragma unroll 8
        for (int h = 0; h < Hh; h++)
            s = fmaf(sf[O_W2 + h], sf[O_W1 + h * W1S + tid], s);
        sf[O_S + tid] = s;
    }

    // ---------------- GEMM A: pre = XX @ W1[:, :64]^T (3xTF32), two 16-row passes --------
    const int nblk = (w & 3) * 32;
    const int hblk = (w >> 2) * 64;

    #pragma unroll 1
    for (int pass = 0; pass < 2; pass++) {
        const int rbase = nblk + 16 * pass;

        float acc[8][4];
        #pragma unroll
        for (int j = 0; j < 8; j++)
            #pragma unroll
            for (int q = 0; q < 4; q++) acc[j][q] = 0.0f;

        #pragma unroll 2
        for (int s = 0; s < 8; s++) {
            const int l  = s >> 2;
            const int c0 = ((8 * s) & 31) + lc;
            uint32_t ah[4], al[4];
            {
                int base = O_XW + (rbase + lr + l) * XWS + c0;
                split_fast(sf[base],               ah[0], al[0]);
                split_fast(sf[base + 8 * XWS],     ah[1], al[1]);
                split_fast(sf[base + 4],           ah[2], al[2]);
                split_fast(sf[base + 8 * XWS + 4], ah[3], al[3]);
            }
            #pragma unroll
            for (int j = 0; j < 8; j++) {
                int hb = O_W1 + (hblk + 8 * j + lr) * W1S + 8 * s + lc;
                uint32_t bh0, bl0, bh1, bl1;
                split_fast(sf[hb],     bh0, bl0);
                split_fast(sf[hb + 4], bh1, bl1);
                mma8(acc[j], ah, bh0, bh1);
                mma8(acc[j], ah, bl0, bl1);
                mma8(acc[j], al, bh0, bh1);
            }
        }

        // epilogue for this pass (h-values hoisted across ci)
        {
            float yyv[2], rp[2] = {0.0f, 0.0f}, jp[2] = {0.0f, 0.0f};
            uint32_t mm0[2] = {0u, 0u}, mm1[2] = {0u, 0u};
            #pragma unroll
            for (int ci = 0; ci < 2; ci++)
                yyv[ci] = sf[O_YY + rbase + 8 * ci + lr + 2];

            #pragma unroll
            for (int j = 0; j < 8; j++) {
                #pragma unroll
                for (int cj = 0; cj < 2; cj++) {
                    const int h = hblk + 8 * j + 2 * lc + cj;
                    const float wl = sf[O_WLAST + h];
                    const float bv = sf[O_B1 + h];
                    const float w2 = sf[O_W2 + h];
                    const uint32_t bitv = 1u << (8 * (j & 3) + 2 * lc + cj);
                    #pragma unroll
                    for (int ci = 0; ci < 2; ci++) {
                        float pre = fmaf(yyv[ci], wl, acc[j][2 * ci + cj]) + bv;
                        float gv = (pre >= 0.0f) ? w2 : SLOPE * w2;
                        rp[ci] = fmaf(pre, gv, rp[ci]);
                        jp[ci] = fmaf(gv, wl, jp[ci]);
                        uint32_t bit = (pre >= 0.0f) ? bitv : 0u;
                        if (j < 4) mm0[ci] |= bit; else mm1[ci] |= bit;
                    }
                }
            }
            #pragma unroll
            for (int ci = 0; ci < 2; ci++) {
                const int row = rbase + 8 * ci + lr;
                uint32_t m0 = mm0[ci], m1 = mm1[ci];
                float rpv = rp[ci], jpv = jp[ci];
                m0 |= __shfl_xor_sync(0xffffffffu, m0, 1);
                m0 |= __shfl_xor_sync(0xffffffffu, m0, 2);
                m1 |= __shfl_xor_sync(0xffffffffu, m1, 1);
                m1 |= __shfl_xor_sync(0xffffffffu, m1, 2);
                rpv += __shfl_xor_sync(0xffffffffu, rpv, 1);
                rpv += __shfl_xor_sync(0xffffffffu, rpv, 2);
                jpv += __shfl_xor_sync(0xffffffffu, jpv, 1);
                jpv += __shfl_xor_sync(0xffffffffu, jpv, 2);
                if (lc == 0) {
                    smemu[O_MASK + row * 4 + (hblk >> 5)]     = m0;
                    smemu[O_MASK + row * 4 + (hblk >> 5) + 1] = m1;
                    atomicAdd(&sf[O_RS + row], rpv);
                    atomicAdd(&sf[O_JS + row], jpv);
                }
            }
        }
    }
    __syncthreads();

    // residual + logdet outputs
    if (tid < 128) {
        const int n = tid;
        out[RES_OFF + ((size_t)(bb * TTt + t0 + n)) * Dd + d] = sf[O_RS + n] + __ldg(&b2[d]);
        float ls = logf(fabsf(sf[O_JS + n]));
        #pragma unroll
        for (int o = 16; o; o >>= 1) ls += __shfl_down_sync(0xffffffffu, ls, o);
        if (lane == 0) atomicAdd(&sf[O_RED], ls);
    }

    // overwrite W1 in place with w2 .* W1 (fp32) for GEMM B
    for (int idx = tid; idx < Hh * 64; idx += 256) {
        const int h = idx >> 6, k = idx & 63;
        sf[O_W1 + h * W1S + k] *= sf[O_W2 + h];
    }
    __syncthreads();

    // ---------------- GEMM B: jac = SLOPE*S + RCOEF*(mask @ (w2.*W1)) ----------
    const int nblk2 = (w & 3) * 32;
    const int kblk  = (w >> 2) * 32;

    float acc2[2][4][4];
    #pragma unroll
    for (int i = 0; i < 2; i++)
        #pragma unroll
        for (int j = 0; j < 4; j++)
            #pragma unroll
            for (int q = 0; q < 4; q++) acc2[i][j][q] = 0.0f;

    #pragma unroll 1
    for (int ws = 0; ws < 4; ws++) {
        uint32_t t00 = smemu[O_MASK + (nblk2 + lr) * 4 + ws] >> lc;
        uint32_t t01 = smemu[O_MASK + (nblk2 + lr + 8) * 4 + ws] >> lc;
        uint32_t t10 = smemu[O_MASK + (nblk2 + 16 + lr) * 4 + ws] >> lc;
        uint32_t t11 = smemu[O_MASK + (nblk2 + 16 + lr + 8) * 4 + ws] >> lc;
        #pragma unroll
        for (int ss = 0; ss < 4; ss++) {
            const int s = 4 * ws + ss;
            uint32_t a[2][4];
            a[0][0] = ((t00 >> (8 * ss)) & 1u) * 0x3F800000u;
            a[0][1] = ((t01 >> (8 * ss)) & 1u) * 0x3F800000u;
            a[0][2] = ((t00 >> (8 * ss + 4)) & 1u) * 0x3F800000u;
            a[0][3] = ((t01 >> (8 * ss + 4)) & 1u) * 0x3F800000u;
            a[1][0] = ((t10 >> (8 * ss)) & 1u) * 0x3F800000u;
            a[1][1] = ((t11 >> (8 * ss)) & 1u) * 0x3F800000u;
            a[1][2] = ((t10 >> (8 * ss + 4)) & 1u) * 0x3F800000u;
            a[1][3] = ((t11 >> (8 * ss + 4)) & 1u) * 0x3F800000u;
            #pragma unroll
            for (int j = 0; j < 4; j++) {
                const int kp = kblk + 8 * j + lr;
                float u0 = sf[O_W1 + (8 * s + lc) * W1S + kp];
                float u1 = sf[O_W1 + (8 * s + lc + 4) * W1S + kp];
                uint32_t bh0, bl0, bh1, bl1;
                split_fast(u0, bh0, bl0);
                split_fast(u1, bh1, bl1);
                #pragma unroll
                for (int i = 0; i < 2; i++) {
                    mma8(acc2[i][j], a[i], bh0, bh1);
                    mma8(acc2[i][j], a[i], bl0, bl1);
                }
            }
        }
    }

    // write hist_jac: jac = SLOPE*S[k] + RCOEF*acc2
    #pragma unroll
    for (int i = 0; i < 2; i++) {
        #pragma unroll
        for (int ci = 0; ci < 2; ci++) {
            const int r = nblk2 + 16 * i + 8 * ci + lr;
            float* hb = out + HIST_OFF + ((size_t)d * NTOT + n0 + r) * 64;
            #pragma unroll
            for (int j = 0; j < 4; j++) {
                const int col = kblk + 8 * j + 2 * lc;
                const float s0 = sf[O_S + col];
                const float s1 = sf[O_S + col + 1];
                float2 v = make_float2(fmaf(RCOEF, acc2[i][j][2 * ci],     SLOPE * s0),
                                       fmaf(RCOEF, acc2[i][j][2 * ci + 1], SLOPE * s1));
                *(float2*)(hb + col) = v;
            }
        }
    }

    __syncthreads();
    if (tid == 0) atomicAdd(&out[SUM_OFF + bb], sf[O_RED]);
}

extern "C" void kernel_launch(void* const* d_in, const int* in_sizes, int n_in,
                              void* d_out, int out_size) {
    const float* x  = (const float*)d_in[0];
    const float* W1 = (const float*)d_in[1];
    const float* b1 = (const float*)d_in[2];
    const float* W2 = (const float*)d_in[3];
    const float* b2 = (const float*)d_in[4];
    float* out = (float*)d_out;

    cudaFuncSetAttribute(fused_mma, cudaFuncAttributeMaxDynamicSharedMemorySize, SMEM_BYTES);

    zero_sum_kernel<<<1, Bb>>>(out);
    fused_mma<<<dim3(Dd, NTILES), 256, SMEM_BYTES>>>(x, W1, b1, W2, b2, out);
}

// round 11
// speedup vs baseline: 1.7170x; 1.1020x over previous
#include <cuda_runtime.h>
#include <cuda_bf16.h>
#include <math.h>
#include <stdint.h>

#define SLOPE 0.01f
constexpr float RCOEF = 1.0f - SLOPE;

// -------- problem constants --------
constexpr int Dd    = 32;
constexpr int Hh    = 128;
constexpr int Bb    = 64;
constexpr int Tt    = 514;
constexpr int TTt   = 512;
constexpr int NTOT  = Bb * TTt;          // 32768
constexpr int NTILE = 128;
constexpr int NTILES = NTOT / NTILE;     // 256

// output layout (reference return order, concatenated)
constexpr size_t RES_OFF  = 0;                        // (64,512,32)
constexpr size_t SUM_OFF  = (size_t)Bb * TTt * Dd;    // (64,)
constexpr size_t HIST_OFF = SUM_OFF + Bb;             // (32,32768,1,64)

// -------- shared offsets (u32 units) — 59 KB, 3 CTAs/SM --------
constexpr int XWS = 36;                  // x-window row stride
constexpr int W1S = 68;                  // W1 row stride
constexpr int O_XW    = 0;                               // 130*36 = 4680 (reused as u_hi after GEMM A)
constexpr int O_W1    = 4680;                            // 128*68 = 8704 (reused as u_lo after GEMM A)
constexpr int O_MASK  = 13384;                           // 128*4
constexpr int O_S     = 13896;                           // 64
constexpr int O_WLAST = 13960;                           // 128
constexpr int O_B1    = 14088;                           // 128
constexpr int O_W2    = 14216;                           // 128
constexpr int O_YY    = 14344;                           // 132
constexpr int O_RS    = 14476;                           // 128
constexpr int O_JS    = 14604;                           // 128
constexpr int O_RED   = 14732;                           // 4
constexpr int SMEM_U32 = 14736;
constexpr int SMEM_BYTES = SMEM_U32 * 4;                 // 58944

// u_* packed arrays (reusing dead regions): [k'=0..63][h_pair=0..63], stride 68
constexpr int O_UH = O_XW;   // 64*68 = 4352 <= 4680
constexpr int O_UL = O_W1;   // 4352 <= 8704
constexpr int UST  = 68;

// CUTLASS-style fast 3xTF32 split: hi = truncate-to-tf32 (LOP3), lo = exact tail (FADD).
__device__ __forceinline__ void split_fast(float v, uint32_t& hi, uint32_t& lo) {
    hi = __float_as_uint(v) & 0xFFFFE000u;
    lo = __float_as_uint(v - __uint_as_float(hi));
}

__device__ __forceinline__ void mma8(float* d, const uint32_t* a, uint32_t b0, uint32_t b1) {
    asm volatile(
        "mma.sync.aligned.m16n8k8.row.col.f32.tf32.tf32.f32 "
        "{%0,%1,%2,%3}, {%4,%5,%6,%7}, {%8,%9}, {%0,%1,%2,%3};"
        : "+f"(d[0]), "+f"(d[1]), "+f"(d[2]), "+f"(d[3])
        : "r"(a[0]), "r"(a[1]), "r"(a[2]), "r"(a[3]), "r"(b0), "r"(b1));
}
__device__ __forceinline__ void mma16bf(float* d, const uint32_t* a, uint32_t b0, uint32_t b1) {
    asm volatile(
        "mma.sync.aligned.m16n8k16.row.col.f32.bf16.bf16.f32 "
        "{%0,%1,%2,%3}, {%4,%5,%6,%7}, {%8,%9}, {%0,%1,%2,%3};"
        : "+f"(d[0]), "+f"(d[1]), "+f"(d[2]), "+f"(d[3])
        : "r"(a[0]), "r"(a[1]), "r"(a[2]), "r"(a[3]), "r"(b0), "r"(b1));
}

// 2 mask bits -> bf16x2 {1.0|0.0, 1.0|0.0}; low half = lower h (bit0)
__device__ __forceinline__ uint32_t mask2bf(uint32_t p) {
    return (p & 1u) * 0x3F80u | (p & 2u) * 0x1FC00000u;
}

__global__ void zero_sum_kernel(float* out) { out[SUM_OFF + threadIdx.x] = 0.0f; }

extern __shared__ uint32_t smemu[];

__global__ __launch_bounds__(256, 3)
void fused_mma(const float* __restrict__ x,  const float* __restrict__ W1,
               const float* __restrict__ b1, const float* __restrict__ W2,
               const float* __restrict__ b2, float* __restrict__ out)
{
    float* sf = (float*)smemu;
    const int tid  = threadIdx.x;
    const int lane = tid & 31;
    const int w    = tid >> 5;
    const int lr   = lane >> 2;   // 0..7
    const int lc   = lane & 3;    // 0..3

    const int d  = blockIdx.x;
    const int n0 = blockIdx.y * NTILE;
    const int bb = n0 / TTt;
    const int t0 = n0 % TTt;

    // ---------------- preamble ----------------
    {
        const float* W1g = W1 + (size_t)d * Hh * 65;
        for (int idx = tid; idx < Hh * 65; idx += 256) {
            int h = idx / 65;
            int k = idx - h * 65;
            float v = W1g[idx];
            if (k == 64) sf[O_WLAST + h] = v;
            else         sf[O_W1 + h * W1S + k] = v;
        }
        const float* xg = x + ((size_t)bb * Tt + t0) * Dd;
        for (int idx = tid; idx < 130 * 32; idx += 256) {
            int r = idx >> 5, c = idx & 31;
            float v = xg[idx];
            sf[O_XW + r * XWS + c] = v;
            if (c == d) sf[O_YY + r] = v;
        }
        if (tid < 128) {
            sf[O_B1 + tid] = b1[(size_t)d * Hh + tid];
            sf[O_W2 + tid] = W2[(size_t)d * Hh + tid];
            sf[O_RS + tid] = 0.0f;
            sf[O_JS + tid] = 0.0f;
        }
        if (tid == 0) sf[O_RED] = 0.0f;
    }
    __syncthreads();

    // colsums S[k] = sum_h w2[h]*W1[h][k]  (original W1; W1 region reused only much later)
    if (tid < 64) {
        float s = 0.0f;
        #pragma unroll 8
        for (int h = 0; h < Hh; h++)
            s = fmaf(sf[O_W2 + h], sf[O_W1 + h * W1S + tid], s);
        sf[O_S + tid] = s;
    }

    // ---------------- GEMM A: pre = XX @ W1[:, :64]^T (3xTF32), two 16-row passes --------
    const int nblk = (w & 3) * 32;
    const int hblk = (w >> 2) * 64;

    #pragma unroll 1
    for (int pass = 0; pass < 2; pass++) {
        const int rbase = nblk + 16 * pass;

        float acc[8][4];
        #pragma unroll
        for (int j = 0; j < 8; j++)
            #pragma unroll
            for (int q = 0; q < 4; q++) acc[j][q] = 0.0f;

        #pragma unroll 2
        for (int s = 0; s < 8; s++) {
            const int l  = s >> 2;
            const int c0 = ((8 * s) & 31) + lc;
            uint32_t ah[4], al[4];
            {
                int base = O_XW + (rbase + lr + l) * XWS + c0;
                split_fast(sf[base],               ah[0], al[0]);
                split_fast(sf[base + 8 * XWS],     ah[1], al[1]);
                split_fast(sf[base + 4],           ah[2], al[2]);
                split_fast(sf[base + 8 * XWS + 4], ah[3], al[3]);
            }
            #pragma unroll
            for (int j = 0; j < 8; j++) {
                int hb = O_W1 + (hblk + 8 * j + lr) * W1S + 8 * s + lc;
                uint32_t bh0, bl0, bh1, bl1;
                split_fast(sf[hb],     bh0, bl0);
                split_fast(sf[hb + 4], bh1, bl1);
                mma8(acc[j], ah, bh0, bh1);
                mma8(acc[j], ah, bl0, bl1);
                mma8(acc[j], al, bh0, bh1);
            }
        }

        // epilogue for this pass
        {
            float yyv[2], rp[2] = {0.0f, 0.0f}, jp[2] = {0.0f, 0.0f};
            uint32_t mm0[2] = {0u, 0u}, mm1[2] = {0u, 0u};
            #pragma unroll
            for (int ci = 0; ci < 2; ci++)
                yyv[ci] = sf[O_YY + rbase + 8 * ci + lr + 2];

            #pragma unroll
            for (int j = 0; j < 8; j++) {
                #pragma unroll
                for (int cj = 0; cj < 2; cj++) {
                    const int h = hblk + 8 * j + 2 * lc + cj;
                    const float wl = sf[O_WLAST + h];
                    const float bv = sf[O_B1 + h];
                    const float w2 = sf[O_W2 + h];
                    const uint32_t bitv = 1u << (8 * (j & 3) + 2 * lc + cj);
                    #pragma unroll
                    for (int ci = 0; ci < 2; ci++) {
                        float pre = fmaf(yyv[ci], wl, acc[j][2 * ci + cj]) + bv;
                        float gv = (pre >= 0.0f) ? w2 : SLOPE * w2;
                        rp[ci] = fmaf(pre, gv, rp[ci]);
                        jp[ci] = fmaf(gv, wl, jp[ci]);
                        uint32_t bit = (pre >= 0.0f) ? bitv : 0u;
                        if (j < 4) mm0[ci] |= bit; else mm1[ci] |= bit;
                    }
                }
            }
            #pragma unroll
            for (int ci = 0; ci < 2; ci++) {
                const int row = rbase + 8 * ci + lr;
                uint32_t m0 = mm0[ci], m1 = mm1[ci];
                float rpv = rp[ci], jpv = jp[ci];
                m0 |= __shfl_xor_sync(0xffffffffu, m0, 1);
                m0 |= __shfl_xor_sync(0xffffffffu, m0, 2);
                m1 |= __shfl_xor_sync(0xffffffffu, m1, 1);
                m1 |= __shfl_xor_sync(0xffffffffu, m1, 2);
                rpv += __shfl_xor_sync(0xffffffffu, rpv, 1);
                rpv += __shfl_xor_sync(0xffffffffu, rpv, 2);
                jpv += __shfl_xor_sync(0xffffffffu, jpv, 1);
                jpv += __shfl_xor_sync(0xffffffffu, jpv, 2);
                if (lc == 0) {
                    smemu[O_MASK + row * 4 + (hblk >> 5)]     = m0;
                    smemu[O_MASK + row * 4 + (hblk >> 5) + 1] = m1;
                    atomicAdd(&sf[O_RS + row], rpv);
                    atomicAdd(&sf[O_JS + row], jpv);
                }
            }
        }
    }
    __syncthreads();

    // residual + logdet outputs
    if (tid < 128) {
        const int n = tid;
        out[RES_OFF + ((size_t)(bb * TTt + t0 + n)) * Dd + d] = sf[O_RS + n] + __ldg(&b2[d]);
        float ls = logf(fabsf(sf[O_JS + n]));
        #pragma unroll
        for (int o = 16; o; o >>= 1) ls += __shfl_down_sync(0xffffffffu, ls, o);
        if (lane == 0) atomicAdd(&sf[O_RED], ls);
    }

    // ---------------- build u = w2 .* W1 as packed bf16 hi/lo --------------------
    // u_hi -> O_UH (dead x-window region), u_lo staged in regs then -> O_UL (W1 region)
    uint32_t lo_st[16];
    #pragma unroll
    for (int t = 0; t < 16; t++) {
        const int idx = tid + 256 * t;          // 0..4095
        const int k = idx >> 6, hp = idx & 63;
        const float u0 = sf[O_W1 + (2 * hp)     * W1S + k] * sf[O_W2 + 2 * hp];
        const float u1 = sf[O_W1 + (2 * hp + 1) * W1S + k] * sf[O_W2 + 2 * hp + 1];
        __nv_bfloat162 hi2 = __floats2bfloat162_rn(u0, u1);   // .x (low) = u0 (even h)
        smemu[O_UH + k * UST + hp] = *(uint32_t*)&hi2;
        const float l0 = u0 - __bfloat162float(hi2.x);
        const float l1 = u1 - __bfloat162float(hi2.y);
        __nv_bfloat162 lo2 = __floats2bfloat162_rn(l0, l1);
        lo_st[t] = *(uint32_t*)&lo2;
    }
    __syncthreads();   // all W1 reads complete before overwrite
    #pragma unroll
    for (int t = 0; t < 16; t++) {
        const int idx = tid + 256 * t;
        const int k = idx >> 6, hp = idx & 63;
        smemu[O_UL + k * UST + hp] = lo_st[t];
    }
    __syncthreads();

    // ---------------- GEMM B: jac = SLOPE*S + RCOEF*(mask @ u)  (bf16 hi+lo, k16) -------
    const int nblk2 = (w & 3) * 32;
    const int kblk  = (w >> 2) * 32;

    float acc2[2][4][4];
    #pragma unroll
    for (int i = 0; i < 2; i++)
        #pragma unroll
        for (int j = 0; j < 4; j++)
            #pragma unroll
            for (int q = 0; q < 4; q++) acc2[i][j][q] = 0.0f;

    #pragma unroll 2
    for (int step = 0; step < 8; step++) {
        const int mw    = step >> 1;
        const int shift = (step & 1) * 16 + 2 * lc;
        uint32_t a[2][4];
        #pragma unroll
        for (int i = 0; i < 2; i++) {
            const uint32_t mLo = smemu[O_MASK + (nblk2 + 16 * i + lr) * 4 + mw];
            const uint32_t mHi = smemu[O_MASK + (nblk2 + 16 * i + lr + 8) * 4 + mw];
            a[i][0] = mask2bf((mLo >> shift) & 3u);
            a[i][1] = mask2bf((mHi >> shift) & 3u);
            a[i][2] = mask2bf((mLo >> (shift + 8)) & 3u);
            a[i][3] = mask2bf((mHi >> (shift + 8)) & 3u);
        }
        const int hp0 = 8 * step + lc;
        #pragma unroll
        for (int j = 0; j < 4; j++) {
            const int kp = kblk + 8 * j + lr;
            const uint32_t bh0 = smemu[O_UH + kp * UST + hp0];
            const uint32_t bh1 = smemu[O_UH + kp * UST + hp0 + 4];
            const uint32_t bl0 = smemu[O_UL + kp * UST + hp0];
            const uint32_t bl1 = smemu[O_UL + kp * UST + hp0 + 4];
            #pragma unroll
            for (int i = 0; i < 2; i++) {
                mma16bf(acc2[i][j], a[i], bh0, bh1);
                mma16bf(acc2[i][j], a[i], bl0, bl1);
            }
        }
    }

    // write hist_jac: jac = SLOPE*S[k] + RCOEF*acc2
    #pragma unroll
    for (int i = 0; i < 2; i++) {
        #pragma unroll
        for (int ci = 0; ci < 2; ci++) {
            const int r = nblk2 + 16 * i + 8 * ci + lr;
            float* hb = out + HIST_OFF + ((size_t)d * NTOT + n0 + r) * 64;
            #pragma unroll
            for (int j = 0; j < 4; j++) {
                const int col = kblk + 8 * j + 2 * lc;
                const float s0 = sf[O_S + col];
                const float s1 = sf[O_S + col + 1];
                float2 v = make_float2(fmaf(RCOEF, acc2[i][j][2 * ci],     SLOPE * s0),
                                       fmaf(RCOEF, acc2[i][j][2 * ci + 1], SLOPE * s1));
                *(float2*)(hb + col) = v;
            }
        }
    }

    __syncthreads();
    if (tid == 0) atomicAdd(&out[SUM_OFF + bb], sf[O_RED]);
}

extern "C" void kernel_launch(void* const* d_in, const int* in_sizes, int n_in,
                              void* d_out, int out_size) {
    const float* x  = (const float*)d_in[0];
    const float* W1 = (const float*)d_in[1];
    const float* b1 = (const float*)d_in[2];
    const float* W2 = (const float*)d_in[3];
    const float* b2 = (const float*)d_in[4];
    float* out = (float*)d_out;

    cudaFuncSetAttribute(fused_mma, cudaFuncAttributeMaxDynamicSharedMemorySize, SMEM_BYTES);

    zero_sum_kernel<<<1, Bb>>>(out);
    fused_mma<<<dim3(Dd, NTILES), 256, SMEM_BYTES>>>(x, W1, b1, W2, b2, out);
}